// round 8
// baseline (speedup 1.0000x reference)
#include <cuda_runtime.h>
#include <math.h>

#define BB 64
#define DD 512
#define HH 8
#define EPSF 1e-8f
#define NTHR 128          // 8 heads x 16 i-values per CTA
#define ITILE 16
#define NTILES (DD / ITILE)   // 32

typedef unsigned long long ull;

__device__ __forceinline__ ull pk2(float lo, float hi) {
    ull r; asm("mov.b64 %0, {%1, %2};" : "=l"(r) : "f"(lo), "f"(hi)); return r;
}
__device__ __forceinline__ void upk2(ull v, float& lo, float& hi) {
    asm("mov.b64 {%0, %1}, %2;" : "=f"(lo), "=f"(hi) : "l"(v));
}
__device__ __forceinline__ ull fma2(ull a, ull b, ull c) {
    ull r; asm("fma.rn.f32x2 %0, %1, %2, %3;" : "=l"(r) : "l"(a), "l"(b), "l"(c)); return r;
}
__device__ __forceinline__ ull add2(ull a, ull b) {
    ull r; asm("add.rn.f32x2 %0, %1, %2;" : "=l"(r) : "l"(a), "l"(b)); return r;
}

__global__ __launch_bounds__(NTHR)
void flattn_kernel(const float* __restrict__ x,
                   const float* __restrict__ alphas,
                   const float* __restrict__ betas,
                   float* __restrict__ out)
{
    __shared__ __align__(16) float xs[DD];
    __shared__ float partial[NTHR];   // [h][i_loc]

    const int b    = blockIdx.y;
    const int tile = blockIdx.x;      // 0..31, block of 16 i-rows
    const int tid  = threadIdx.x;
    const int h     = tid >> 4;       // 0..7
    const int i_loc = tid & 15;       // 0..15
    const int i     = tile * ITILE + i_loc;

    // Stage x row in shared (vectorized).
    const float4* xrow4 = (const float4*)(x + b * DD);
    float4* xs4w = (float4*)xs;
    #pragma unroll
    for (int k = tid; k < DD / 4; k += NTHR) xs4w[k] = xrow4[k];
    __syncthreads();

    // Per-thread head params (tiny, L2-resident).
    const float aq = alphas[h * 3 + 0];
    const float ak = alphas[h * 3 + 1];
    const float av = alphas[h * 3 + 2];
    const float bq = betas[h * 3 + 0];
    const float bk = betas[h * 3 + 1];

    const float inv_sqrt_d = 0.044194173824159216f;  // 1/sqrt(512)
    const float INV_L2E    = 0.6931471805599453f;    // 1/log2(e) = ln(2)

    // Work in the L2E-scaled domain: d' = d/L2E, eps' = eps/L2E, so that
    // rcp(|d'| + eps') = L2E * s  feeds ex2 directly (no packing between MUFUs).
    const float xi  = xs[i];
    const float c   = bq - fmaf(ak, xi, bk);   // q_j - k_i = aq*x_j + c
    const float aqs = aq * INV_L2E;
    const float cs  = c  * INV_L2E;
    const float EPS_S = EPSF * INV_L2E;

    const ull aq2 = pk2(aqs, aqs);
    const ull c2  = pk2(cs, cs);

    const float4* xs4 = (const float4*)xs;

    // ---- Pass 1: tmin' = min_j |aqs*x_j + cs|  (scalar FFMA + FMNMX) ----
    float t0 = 3.0e38f, t1 = 3.0e38f, t2 = 3.0e38f, t3 = 3.0e38f;
    #pragma unroll 8
    for (int j4 = 0; j4 < DD / 4; j4++) {
        float4 xv = xs4[j4];
        t0 = fminf(t0, fabsf(fmaf(aqs, xv.x, cs)));
        t1 = fminf(t1, fabsf(fmaf(aqs, xv.y, cs)));
        t2 = fminf(t2, fabsf(fmaf(aqs, xv.z, cs)));
        t3 = fminf(t3, fabsf(fmaf(aqs, xv.w, cs)));
    }
    float tmin = fminf(fminf(t0, t1), fminf(t2, t3)) + EPS_S;
    float mL2E;   // = L2E * max_j s_j  (rcp monotone decreasing)
    asm("rcp.approx.f32 %0, %1;" : "=f"(mL2E) : "f"(tmin));
    const float negm = -mL2E;

    // ---- Pass 2: e = 2^(rcp(t') - m*L2E); accumulate sum(e), sum(e*x) ----
    const ulonglong2* xs2 = (const ulonglong2*)xs;
    ull w2 = 0ULL, w2b = 0ULL, wx2 = 0ULL, wx2b = 0ULL;
    #pragma unroll 8
    for (int jq = 0; jq < DD / 4; jq++) {
        ulonglong2 xq = xs2[jq];       // two packed f32x2 operands, one LDS.128
        ull x01 = xq.x, x23 = xq.y;

        ull d01 = fma2(aq2, x01, c2);
        ull d23 = fma2(aq2, x23, c2);
        float da, db, dc, dd;
        upk2(d01, da, db);
        upk2(d23, dc, dd);

        float ta = fabsf(da) + EPS_S;
        float tb = fabsf(db) + EPS_S;
        float tc = fabsf(dc) + EPS_S;
        float td = fabsf(dd) + EPS_S;

        float ra, rb, rc, rd;
        asm("rcp.approx.f32 %0, %1;" : "=f"(ra) : "f"(ta));
        asm("rcp.approx.f32 %0, %1;" : "=f"(rb) : "f"(tb));
        asm("rcp.approx.f32 %0, %1;" : "=f"(rc) : "f"(tc));
        asm("rcp.approx.f32 %0, %1;" : "=f"(rd) : "f"(td));

        float aa = ra + negm;
        float ab = rb + negm;
        float ac = rc + negm;
        float ad = rd + negm;

        float ea, eb, ec, ed;
        asm("ex2.approx.f32 %0, %1;" : "=f"(ea) : "f"(aa));
        asm("ex2.approx.f32 %0, %1;" : "=f"(eb) : "f"(ab));
        asm("ex2.approx.f32 %0, %1;" : "=f"(ec) : "f"(ac));
        asm("ex2.approx.f32 %0, %1;" : "=f"(ed) : "f"(ad));

        ull e01 = pk2(ea, eb);
        ull e23 = pk2(ec, ed);
        w2   = add2(w2,  e01);
        w2b  = add2(w2b, e23);
        wx2  = fma2(e01, x01, wx2);
        wx2b = fma2(e23, x23, wx2b);
    }
    float wl, wh, wbl, wbh, wxl, wxh, wxbl, wxbh;
    upk2(w2, wl, wh);
    upk2(w2b, wbl, wbh);
    upk2(wx2, wxl, wxh);
    upk2(wx2b, wxbl, wxbh);
    float wsum = (wl + wh) + (wbl + wbh);
    float wx   = (wxl + wxh) + (wxbl + wxbh);

    float rw;
    asm("rcp.approx.f32 %0, %1;" : "=f"(rw) : "f"(wsum));
    // contribution of head h to output i: (av * wx/wsum) / sqrt(d)
    partial[tid] = av * inv_sqrt_d * (wx * rw);
    __syncthreads();

    // ---- Cross-head sum (8 values per output), single coalesced store ----
    if (tid < ITILE) {
        float bconst = 0.0f;
        #pragma unroll
        for (int hh = 0; hh < HH; hh++) bconst += betas[hh * 3 + 2];

        float s = 0.0f;
        #pragma unroll
        for (int hh = 0; hh < HH; hh++) s += partial[hh * ITILE + tid];

        out[b * DD + tile * ITILE + tid] =
            xs[tile * ITILE + tid] + s + bconst * inv_sqrt_d;
    }
}

extern "C" void kernel_launch(void* const* d_in, const int* in_sizes, int n_in,
                              void* d_out, int out_size)
{
    const float* x      = (const float*)d_in[0];
    const float* alphas = (const float*)d_in[1];
    const float* betas  = (const float*)d_in[2];
    float* out = (float*)d_out;

    dim3 grid(NTILES, BB);   // (32, 64) = 2048 CTAs
    dim3 block(NTHR);
    flattn_kernel<<<grid, block>>>(x, alphas, betas, out);
}